// round 1
// baseline (speedup 1.0000x reference)
#include <cuda_runtime.h>
#include <cuda_bf16.h>
#include <stdint.h>

// Problem constants
#define NROWS 16384      // B*L = 16*1024
#define DIM   768
#define NLAT  5000
#define NLATP 5120       // padded latent count (mult of 128)
#define CHARS 8

// ---------------- scratch (static __device__ — no allocations) ----------------
__device__ int            g_is64;                        // 1 if x is int64, 0 if int32
__device__ __nv_bfloat16  g_L[(size_t)NLATP * DIM];      // latent_mat bf16, zero-padded rows
__device__ float          g_E[(size_t)NROWS * DIM];      // lang_emb fp32
__device__ __nv_bfloat16  g_Eb[(size_t)NROWS * DIM];     // lang_emb bf16
__device__ float          g_S[(size_t)NROWS * NLATP];    // scores fp32
__device__ __nv_bfloat16  g_Dist[(size_t)NROWS * NLATP]; // softmax dist bf16 (pad cols = 0)
__device__ float          g_Lat[(size_t)NROWS * DIM];    // latent_emb fp32

// ---------------- dtype detection ----------------
// If x stored as int64 (values < 30000), every odd int32 word is 0.
__global__ void detect_kernel(const int* __restrict__ x32) {
    if (threadIdx.x == 0 && blockIdx.x == 0) {
        int is64 = 1;
        for (int i = 1; i < 128; i += 2)
            if (x32[i] != 0) { is64 = 0; break; }
        g_is64 = is64;
    }
}

// ---------------- latent -> bf16 with zero padding ----------------
__global__ void conv_latent_kernel(const float* __restrict__ L) {
    int idx = blockIdx.x * 256 + threadIdx.x;
    if (idx < NLATP * DIM) {
        int r = idx / DIM;
        float v = (r < NLAT) ? L[idx] : 0.0f;
        g_L[idx] = __float2bfloat16(v);
    }
}

// ---------------- embed: lang_emb = tanh(masked_mean(char_emb[x])) ----------------
__global__ void embed_kernel(const void* __restrict__ xv, const float* __restrict__ ce) {
    __shared__ int ids[CHARS];
    __shared__ float s_inv;
    int n = blockIdx.x;
    if (threadIdx.x < CHARS) {
        int id;
        if (g_is64) id = (int)((const long long*)xv)[(size_t)n * CHARS + threadIdx.x];
        else        id = ((const int*)xv)[(size_t)n * CHARS + threadIdx.x];
        ids[threadIdx.x] = id;
    }
    __syncthreads();
    if (threadIdx.x == 0) {
        int c = 0;
        #pragma unroll
        for (int i = 0; i < CHARS; i++) c += (ids[i] != 0);
        if (c < 1) c = 1;
        s_inv = 1.0f / (float)c;
    }
    __syncthreads();
    float inv = s_inv;
    for (int d = threadIdx.x; d < DIM; d += 256) {
        float s = 0.0f;
        #pragma unroll
        for (int c = 0; c < CHARS; c++) {
            int id = ids[c];
            if (id != 0) s += ce[(size_t)id * DIM + d];
        }
        float v = tanhf(s * inv);
        size_t o = (size_t)n * DIM + d;
        g_E[o]  = v;
        g_Eb[o] = __float2bfloat16(v);
    }
}

// ---------------- bf16 mma.sync GEMM ----------------
// C[M,N] (fp32) = A[M,K] (bf16 row-major, lda=K) * op(B)
//   b_nt=1: B is [N,K] row-major (ldb=K)      -> C = A * B^T   (GEMM1: scores)
//   b_nt=0: B is [K,N] row-major (ldb=N)      -> C = A * B     (GEMM2: latent_emb)
// Tiles: BM=128, BN=128, BK=32. 256 threads = 8 warps (4m x 2n), warp tile 32x64.
#define BM 128
#define BN 128
#define BK 32
#define LDT 40   // BK + 8 pad (halves)

__global__ __launch_bounds__(256) void gemm_kernel(
    const __nv_bfloat16* __restrict__ A, int lda,
    const __nv_bfloat16* __restrict__ B, int ldb,
    float* __restrict__ C, int ldc,
    int K, int b_nt)
{
    __shared__ __nv_bfloat16 As[BM * LDT];
    __shared__ __nv_bfloat16 Bs[BN * LDT];

    int tid = threadIdx.x;
    int lane = tid & 31, wid = tid >> 5;
    int warp_m = wid >> 1, warp_n = wid & 1;
    int bm = blockIdx.y * BM, bn = blockIdx.x * BN;

    float acc[2][8][4];
    #pragma unroll
    for (int i = 0; i < 2; i++)
        #pragma unroll
        for (int j = 0; j < 8; j++)
            #pragma unroll
            for (int t = 0; t < 4; t++) acc[i][j][t] = 0.0f;

    for (int k0 = 0; k0 < K; k0 += BK) {
        // A tile: 128x32 halves = 2048 u32, 8 per thread
        #pragma unroll
        for (int i = 0; i < 8; i++) {
            int idx = tid + i * 256;
            int r = idx >> 4, c2 = idx & 15;
            uint32_t v = *(const uint32_t*)(A + (size_t)(bm + r) * lda + k0 + c2 * 2);
            *(uint32_t*)(As + r * LDT + c2 * 2) = v;
        }
        if (b_nt) {
            #pragma unroll
            for (int i = 0; i < 8; i++) {
                int idx = tid + i * 256;
                int r = idx >> 4, c2 = idx & 15;
                uint32_t v = *(const uint32_t*)(B + (size_t)(bn + r) * ldb + k0 + c2 * 2);
                *(uint32_t*)(Bs + r * LDT + c2 * 2) = v;
            }
        } else {
            // transpose-load: Bs[n][k] = B[k0+k][bn+n]
            #pragma unroll
            for (int i = 0; i < 16; i++) {
                int idx = tid + i * 256;
                int k = idx >> 7, nn = idx & 127;
                Bs[nn * LDT + k] = B[(size_t)(k0 + k) * ldb + bn + nn];
            }
        }
        __syncthreads();

        #pragma unroll
        for (int kk = 0; kk < BK; kk += 16) {
            uint32_t af[2][4];
            #pragma unroll
            for (int mt = 0; mt < 2; mt++) {
                int row = warp_m * 32 + mt * 16 + (lane >> 2);
                int col = kk + (lane & 3) * 2;
                const __nv_bfloat16* p = As + row * LDT + col;
                af[mt][0] = *(const uint32_t*)(p);
                af[mt][1] = *(const uint32_t*)(p + 8 * LDT);
                af[mt][2] = *(const uint32_t*)(p + 8);
                af[mt][3] = *(const uint32_t*)(p + 8 * LDT + 8);
            }
            uint32_t bfr[8][2];
            #pragma unroll
            for (int nt = 0; nt < 8; nt++) {
                int nr = warp_n * 64 + nt * 8 + (lane >> 2);
                int col = kk + (lane & 3) * 2;
                const __nv_bfloat16* p = Bs + nr * LDT + col;
                bfr[nt][0] = *(const uint32_t*)(p);
                bfr[nt][1] = *(const uint32_t*)(p + 8);
            }
            #pragma unroll
            for (int mt = 0; mt < 2; mt++)
                #pragma unroll
                for (int nt = 0; nt < 8; nt++) {
                    asm volatile(
                        "mma.sync.aligned.m16n8k16.row.col.f32.bf16.bf16.f32 "
                        "{%0,%1,%2,%3}, {%4,%5,%6,%7}, {%8,%9}, {%0,%1,%2,%3};\n"
                        : "+f"(acc[mt][nt][0]), "+f"(acc[mt][nt][1]),
                          "+f"(acc[mt][nt][2]), "+f"(acc[mt][nt][3])
                        : "r"(af[mt][0]), "r"(af[mt][1]), "r"(af[mt][2]), "r"(af[mt][3]),
                          "r"(bfr[nt][0]), "r"(bfr[nt][1]));
                }
        }
        __syncthreads();
    }

    // store
    #pragma unroll
    for (int mt = 0; mt < 2; mt++)
        #pragma unroll
        for (int nt = 0; nt < 8; nt++) {
            int row = bm + warp_m * 32 + mt * 16 + (lane >> 2);
            int col = bn + warp_n * 64 + nt * 8 + (lane & 3) * 2;
            C[(size_t)row * ldc + col]           = acc[mt][nt][0];
            C[(size_t)row * ldc + col + 1]       = acc[mt][nt][1];
            C[(size_t)(row + 8) * ldc + col]     = acc[mt][nt][2];
            C[(size_t)(row + 8) * ldc + col + 1] = acc[mt][nt][3];
        }
}

// ---------------- softmax over 5000 scores per row, write bf16 dist (pad = 0) ----------------
__global__ void softmax_kernel() {
    int n = blockIdx.x;
    const float* s = g_S + (size_t)n * NLATP;
    __shared__ float red[256];

    float m = -1e30f;
    for (int i = threadIdx.x; i < NLAT; i += 256) m = fmaxf(m, s[i]);
    red[threadIdx.x] = m; __syncthreads();
    for (int off = 128; off; off >>= 1) {
        if (threadIdx.x < off) red[threadIdx.x] = fmaxf(red[threadIdx.x], red[threadIdx.x + off]);
        __syncthreads();
    }
    m = red[0]; __syncthreads();

    float sum = 0.0f;
    for (int i = threadIdx.x; i < NLAT; i += 256) sum += __expf(s[i] - m);
    red[threadIdx.x] = sum; __syncthreads();
    for (int off = 128; off; off >>= 1) {
        if (threadIdx.x < off) red[threadIdx.x] += red[threadIdx.x + off];
        __syncthreads();
    }
    float inv = 1.0f / red[0];

    __nv_bfloat16* d = g_Dist + (size_t)n * NLATP;
    for (int i = threadIdx.x; i < NLAT; i += 256) d[i] = __float2bfloat16(__expf(s[i] - m) * inv);
    for (int i = NLAT + threadIdx.x; i < NLATP; i += 256) d[i] = __float2bfloat16(0.0f);
}

// ---------------- epilogue: out = lang_emb + latent_emb, with special-token override ----------------
__global__ void epilogue_kernel(const void* __restrict__ xv, const float* __restrict__ ce,
                                float* __restrict__ out) {
    int idx = blockIdx.x * 256 + threadIdx.x;
    if (idx >= NROWS * DIM) return;
    int n = idx / DIM, d = idx - n * DIM;
    int first;
    if (g_is64) first = (int)((const long long*)xv)[(size_t)n * CHARS];
    else        first = ((const int*)xv)[(size_t)n * CHARS];
    float v;
    if (first < 4) v = ce[(size_t)first * DIM + d];
    else           v = g_E[idx] + g_Lat[idx];
    out[idx] = v;
}

// ---------------- launch ----------------
extern "C" void kernel_launch(void* const* d_in, const int* in_sizes, int n_in,
                              void* d_out, int out_size) {
    const void*  x    = d_in[0];                 // [16,1024,8] int32 or int64
    const float* ce   = (const float*)d_in[1];   // [30000,768]
    const float* lm   = (const float*)d_in[2];   // [5000,768]
    float* out = (float*)d_out;                  // [16,1024,768]

    detect_kernel<<<1, 32>>>((const int*)x);
    conv_latent_kernel<<<(NLATP * DIM + 255) / 256, 256>>>(lm);
    embed_kernel<<<NROWS, 256>>>(x, ce);

    // GEMM1: scores[NROWS, NLATP] = Eb[NROWS, DIM] * L^T   (NT)
    {
        dim3 grid(NLATP / BN, NROWS / BM);
        gemm_kernel<<<grid, 256>>>(g_Eb, DIM, g_L, DIM, g_S, NLATP, DIM, 1);
    }

    softmax_kernel<<<NROWS, 256>>>();

    // GEMM2: latent_emb[NROWS, DIM] = Dist[NROWS, NLATP] * L   (NN)
    {
        dim3 grid(DIM / BN, NROWS / BM);
        gemm_kernel<<<grid, 256>>>(g_Dist, NLATP, g_L, DIM, g_Lat, DIM, NLATP, 0);
    }

    epilogue_kernel<<<(NROWS * DIM + 255) / 256, 256>>>(x, ce, out);
}

// round 3
// speedup vs baseline: 1.7249x; 1.7249x over previous
#include <cuda_runtime.h>
#include <cuda_bf16.h>
#include <stdint.h>

#define NROWS 16384
#define DIM   768
#define NLAT  5000
#define NLATP 5120
#define CHARS 8

// ---- GEMM tiling ----
#define BM 128
#define BN 128
#define BK 32
#define NST 4
#define ASTB (BM*BK*2)           // 8 KB A stage
#define BSTB (BN*BK*2)           // 8 KB B stage
#define STB  (ASTB+BSTB)         // 16 KB per stage
#define SMEM_TOTAL (NST*STB)     // 64 KB

// ---------------- scratch ----------------
__device__ int g_is64;
__device__ __align__(128) __nv_bfloat16 g_L [(size_t)NLATP*DIM];   // latent [5120,768] K-major, pad rows 0
__device__ __align__(128) __nv_bfloat16 g_LT[(size_t)DIM*NLATP];   // latent^T [768,5120] K-major, pad cols 0
__device__ __align__(128) float         g_E [(size_t)NROWS*DIM];   // lang_emb fp32
__device__ __align__(128) __nv_bfloat16 g_Eb[(size_t)NROWS*DIM];   // lang_emb bf16
__device__ __align__(128) float         g_S [(size_t)NROWS*NLATP]; // scores fp32
__device__ __align__(128) __nv_bfloat16 g_Dist[(size_t)NROWS*NLATP];

// ---------------- helpers ----------------
__device__ __forceinline__ uint32_t smem_u32(const void* p) {
    uint32_t a;
    asm("{ .reg .u64 t; cvta.to.shared.u64 t, %1; cvt.u32.u64 %0, t; }" : "=r"(a) : "l"(p));
    return a;
}
__device__ __forceinline__ uint32_t swz(uint32_t off) {        // 64B-row swizzle
    return off ^ (((off >> 7) & 3u) << 4);
}
#define CP_ASYNC16(dst, src) \
    asm volatile("cp.async.cg.shared.global [%0], [%1], 16;" :: "r"(dst), "l"(src) : "memory")
#define CP_COMMIT() asm volatile("cp.async.commit_group;" ::: "memory")
#define CP_WAIT2()  asm volatile("cp.async.wait_group 2;"  ::: "memory")

#define LDMX4(r0,r1,r2,r3,a) \
    asm volatile("ldmatrix.sync.aligned.m8n8.x4.shared.b16 {%0,%1,%2,%3}, [%4];" \
        : "=r"(r0), "=r"(r1), "=r"(r2), "=r"(r3) : "r"(a))

#define MMA16816(d, a0,a1,a2,a3, b0,b1) \
    asm volatile("mma.sync.aligned.m16n8k16.row.col.f32.bf16.bf16.f32 " \
        "{%0,%1,%2,%3}, {%4,%5,%6,%7}, {%8,%9}, {%0,%1,%2,%3};" \
        : "+f"((d)[0]), "+f"((d)[1]), "+f"((d)[2]), "+f"((d)[3]) \
        : "r"(a0), "r"(a1), "r"(a2), "r"(a3), "r"(b0), "r"(b1))

// ---------------- small kernels ----------------
__global__ void detect_kernel(const int* __restrict__ x32) {
    if (threadIdx.x == 0 && blockIdx.x == 0) {
        int is64 = 1;
        for (int i = 1; i < 128; i += 2)
            if (x32[i] != 0) { is64 = 0; break; }
        g_is64 = is64;
    }
}

__global__ void conv_latent_kernel(const float* __restrict__ L) {
    int idx = blockIdx.x * 256 + threadIdx.x;
    if (idx < NLATP * DIM) {
        int r = idx / DIM;
        float v = (r < NLAT) ? L[idx] : 0.0f;
        g_L[idx] = __float2bfloat16(v);
    }
}

__global__ void transpose_latent_kernel(const float* __restrict__ L) {
    __shared__ float t[32][33];
    int k0 = blockIdx.x * 32, d0 = blockIdx.y * 32;
    #pragma unroll
    for (int i = 0; i < 4; i++) {
        int k = k0 + threadIdx.y + 8 * i;
        t[threadIdx.y + 8 * i][threadIdx.x] =
            (k < NLAT) ? L[(size_t)k * DIM + d0 + threadIdx.x] : 0.0f;
    }
    __syncthreads();
    #pragma unroll
    for (int i = 0; i < 4; i++) {
        int d = d0 + threadIdx.y + 8 * i;
        g_LT[(size_t)d * NLATP + k0 + threadIdx.x] =
            __float2bfloat16(t[threadIdx.x][threadIdx.y + 8 * i]);
    }
}

__global__ void embed_kernel(const void* __restrict__ xv, const float* __restrict__ ce) {
    __shared__ int ids[CHARS];
    __shared__ float s_inv;
    int n = blockIdx.x;
    if (threadIdx.x < CHARS) {
        int id;
        if (g_is64) id = (int)((const long long*)xv)[(size_t)n * CHARS + threadIdx.x];
        else        id = ((const int*)xv)[(size_t)n * CHARS + threadIdx.x];
        ids[threadIdx.x] = id;
    }
    __syncthreads();
    if (threadIdx.x == 0) {
        int c = 0;
        #pragma unroll
        for (int i = 0; i < CHARS; i++) c += (ids[i] != 0);
        if (c < 1) c = 1;
        s_inv = 1.0f / (float)c;
    }
    __syncthreads();
    float inv = s_inv;
    for (int d = threadIdx.x; d < DIM; d += 256) {
        float s = 0.0f;
        #pragma unroll
        for (int c = 0; c < CHARS; c++) {
            int id = ids[c];
            if (id != 0) s += ce[(size_t)id * DIM + d];
        }
        float v = tanhf(s * inv);
        size_t o = (size_t)n * DIM + d;
        g_E[o]  = v;
        g_Eb[o] = __float2bfloat16(v);
    }
}

__global__ void softmax_kernel() {
    __shared__ float sc[NLAT];
    __shared__ float red[256];
    int n = blockIdx.x, t = threadIdx.x;
    const float* s = g_S + (size_t)n * NLATP;

    float m = -1e30f;
    for (int i = t; i < NLAT; i += 256) { float v = s[i]; sc[i] = v; m = fmaxf(m, v); }
    red[t] = m; __syncthreads();
    for (int off = 128; off; off >>= 1) {
        if (t < off) red[t] = fmaxf(red[t], red[t + off]);
        __syncthreads();
    }
    m = red[0]; __syncthreads();

    float sum = 0.0f;
    for (int i = t; i < NLAT; i += 256) sum += __expf(sc[i] - m);
    red[t] = sum; __syncthreads();
    for (int off = 128; off; off >>= 1) {
        if (t < off) red[t] += red[t + off];
        __syncthreads();
    }
    float inv = 1.0f / red[0];

    __nv_bfloat16* d = g_Dist + (size_t)n * NLATP;
    for (int i = t; i < NLAT; i += 256) d[i] = __float2bfloat16(__expf(sc[i] - m) * inv);
    for (int i = NLAT + t; i < NLATP; i += 256) d[i] = __float2bfloat16(0.0f);
}

// ---------------- pipelined mma.sync GEMM ----------------
// C[BM,BN] = A[M,K] * B[N,K]^T, both K-major bf16.
// mode 1: C -> g_S (fp32 scores)
// mode 2: out = g_E + C with special-token override
__global__ __launch_bounds__(256, 2) void gemm_mma(
    const __nv_bfloat16* __restrict__ A, size_t lda,
    const __nv_bfloat16* __restrict__ B, size_t ldb,
    int nchunks, int mode,
    const void* __restrict__ xv, const float* __restrict__ ce,
    float* __restrict__ out)
{
    extern __shared__ char smem[];
    uint32_t sbase = smem_u32(smem);
    int tid = threadIdx.x, lane = tid & 31, wid = tid >> 5;
    int warp_m = wid >> 1, warp_n = wid & 1;
    size_t bm = (size_t)blockIdx.y * BM, bn = (size_t)blockIdx.x * BN;

    // gmem source base for this thread's cp.async elements
    int ld_row = tid >> 2;          // 0..63  (row step of 64 per pass)
    int ld_c   = tid & 3;           // 16B chunk
    const char* agp = (const char*)(A + (bm + (size_t)ld_row) * lda) + ld_c * 16;
    const char* bgp = (const char*)(B + (bn + (size_t)ld_row) * ldb) + ld_c * 16;
    size_t astep = 64 * lda * 2, bstep = 64 * ldb * 2;
    uint32_t soff = swz((uint32_t)ld_row * 64 + (uint32_t)ld_c * 16);
    uint32_t soff2 = swz((uint32_t)(ld_row + 64) * 64 + (uint32_t)ld_c * 16);

    // fragment lane addressing (within a stage tile, before ks/mt/nt offsets)
    int fidx = lane & 7;
    int a_row0 = warp_m * 32 + ((lane >> 3) & 1) * 8 + fidx;  // + mt*16
    int a_cb   = lane >> 4;                                    // k16-half
    int b_row0 = warp_n * 64 + ((lane >> 4) << 3) + fidx;      // + nt*16
    int b_cb   = (lane >> 3) & 1;

    float acc[2][8][4];
    #pragma unroll
    for (int i = 0; i < 2; i++)
        #pragma unroll
        for (int j = 0; j < 8; j++)
            #pragma unroll
            for (int q = 0; q < 4; q++) acc[i][j][q] = 0.0f;

    // prologue: stages 0..NST-2
    #pragma unroll
    for (int s = 0; s < NST - 1; s++) {
        uint32_t sa = sbase + s * STB, sb = sa + ASTB;
        size_t koff = (size_t)s * BK * 2;                      // bytes along K
        CP_ASYNC16(sa + soff,  agp + koff);
        CP_ASYNC16(sa + soff2, agp + astep + koff);
        CP_ASYNC16(sb + soff,  bgp + koff);
        CP_ASYNC16(sb + soff2, bgp + bstep + koff);
        CP_COMMIT();
    }

    for (int i = 0; i < nchunks; i++) {
        CP_WAIT2();
        __syncthreads();

        int pf = i + NST - 1;
        if (pf < nchunks) {
            int s = pf & (NST - 1);
            uint32_t sa = sbase + s * STB, sb = sa + ASTB;
            size_t koff = (size_t)pf * BK * 2;
            CP_ASYNC16(sa + soff,  agp + koff);
            CP_ASYNC16(sa + soff2, agp + astep + koff);
            CP_ASYNC16(sb + soff,  bgp + koff);
            CP_ASYNC16(sb + soff2, bgp + bstep + koff);
        }
        CP_COMMIT();

        uint32_t sa = sbase + (i & (NST - 1)) * STB, sb = sa + ASTB;
        #pragma unroll
        for (int ks = 0; ks < 2; ks++) {
            uint32_t af[2][4], bf[4][4];
            #pragma unroll
            for (int mt = 0; mt < 2; mt++) {
                int row = a_row0 + mt * 16;
                uint32_t ad = sa + swz((uint32_t)row * 64 + (uint32_t)(ks * 2 + a_cb) * 16);
                LDMX4(af[mt][0], af[mt][1], af[mt][2], af[mt][3], ad);
            }
            #pragma unroll
            for (int nt = 0; nt < 4; nt++) {
                int row = b_row0 + nt * 16;
                uint32_t bd = sb + swz((uint32_t)row * 64 + (uint32_t)(ks * 2 + b_cb) * 16);
                LDMX4(bf[nt][0], bf[nt][1], bf[nt][2], bf[nt][3], bd);
            }
            #pragma unroll
            for (int mt = 0; mt < 2; mt++)
                #pragma unroll
                for (int nt = 0; nt < 4; nt++) {
                    MMA16816(acc[mt][2 * nt],     af[mt][0], af[mt][1], af[mt][2], af[mt][3],
                             bf[nt][0], bf[nt][1]);
                    MMA16816(acc[mt][2 * nt + 1], af[mt][0], af[mt][1], af[mt][2], af[mt][3],
                             bf[nt][2], bf[nt][3]);
                }
        }
    }

    // ---- epilogue ----
    int rbase = warp_m * 32 + (lane >> 2);
    int cbase = warp_n * 64 + (lane & 3) * 2;
    if (mode == 1) {
        #pragma unroll
        for (int mt = 0; mt < 2; mt++)
            #pragma unroll
            for (int h = 0; h < 2; h++) {
                size_t row = bm + rbase + mt * 16 + h * 8;
                float* dst = g_S + row * NLATP + bn + cbase;
                #pragma unroll
                for (int nt = 0; nt < 8; nt++)
                    *(float2*)(dst + nt * 8) =
                        make_float2(acc[mt][nt][2 * h], acc[mt][nt][2 * h + 1]);
            }
    } else {
        #pragma unroll
        for (int mt = 0; mt < 2; mt++)
            #pragma unroll
            for (int h = 0; h < 2; h++) {
                size_t row = bm + rbase + mt * 16 + h * 8;
                int first;
                if (g_is64) first = (int)((const long long*)xv)[row * CHARS];
                else        first = ((const int*)xv)[row * CHARS];
                size_t cb = bn + cbase;
                float* dst = out + row * DIM + cb;
                if (first < 4) {
                    const float* cp = ce + (size_t)first * DIM + cb;
                    #pragma unroll
                    for (int nt = 0; nt < 8; nt++)
                        *(float2*)(dst + nt * 8) = make_float2(cp[nt * 8], cp[nt * 8 + 1]);
                } else {
                    const float* ep = g_E + row * DIM + cb;
                    #pragma unroll
                    for (int nt = 0; nt < 8; nt++)
                        *(float2*)(dst + nt * 8) =
                            make_float2(ep[nt * 8]     + acc[mt][nt][2 * h],
                                        ep[nt * 8 + 1] + acc[mt][nt][2 * h + 1]);
                }
            }
    }
}

// ---------------- launch ----------------
extern "C" void kernel_launch(void* const* d_in, const int* in_sizes, int n_in,
                              void* d_out, int out_size) {
    const void*  x  = d_in[0];
    const float* ce = (const float*)d_in[1];
    const float* lm = (const float*)d_in[2];
    float* out = (float*)d_out;

    cudaFuncSetAttribute(gemm_mma, cudaFuncAttributeMaxDynamicSharedMemorySize, SMEM_TOTAL);

    detect_kernel<<<1, 32>>>((const int*)x);
    conv_latent_kernel<<<(NLATP * DIM + 255) / 256, 256>>>(lm);
    {
        dim3 blk(32, 8), grd(NLATP / 32, DIM / 32);
        transpose_latent_kernel<<<grd, blk>>>(lm);
    }
    embed_kernel<<<NROWS, 256>>>(x, ce);

    // GEMM1: scores = Eb[16384,768] * L[5120,768]^T
    {
        dim3 grid(NLATP / BN, NROWS / BM);
        gemm_mma<<<grid, 256, SMEM_TOTAL>>>(g_Eb, (size_t)DIM, g_L, (size_t)DIM,
                                            DIM / BK, 1, x, ce, nullptr);
    }

    softmax_kernel<<<NROWS, 256>>>();

    // GEMM2 (+fused epilogue): out = E + Dist[16384,5120] * LT[768,5120]^T
    {
        dim3 grid(DIM / BN, NROWS / BM);
        gemm_mma<<<grid, 256, SMEM_TOTAL>>>(g_Dist, (size_t)NLATP, g_LT, (size_t)NLATP,
                                            NLATP / BK, 2, x, ce, out);
    }
}